// round 3
// baseline (speedup 1.0000x reference)
#include <cuda_runtime.h>

#define S_TOK 16384
#define DDIM  4096
#define NEXP  64
#define CAP   320
#define BM    128
#define BK    32
#define NTHREADS 256

// ---------------- device scratch (no allocations allowed) ----------------
__device__ int   g_e1[S_TOK];
__device__ int   g_e2[S_TOK];
__device__ int   g_want2[S_TOK];
__device__ float g_g1n[S_TOK];
__device__ float g_g2n[S_TOK];

typedef unsigned long long u64;

__device__ __forceinline__ u64 fma2(u64 a, u64 b, u64 c) {
    u64 d;
    asm("fma.rn.f32x2 %0, %1, %2, %3;" : "=l"(d) : "l"(a), "l"(b), "l"(c));
    return d;
}
__device__ __forceinline__ u64 add2(u64 a, u64 b) {
    u64 d;
    asm("add.rn.f32x2 %0, %1, %2;" : "=l"(d) : "l"(a), "l"(b));
    return d;
}

__device__ __forceinline__ unsigned rotl32(unsigned v, int s) {
    return (v << s) | (v >> (32 - s));
}

// Threefry-2x32, 20 rounds, key = (0, 1)  [jax.random.key(1)]
__device__ __forceinline__ void threefry01(unsigned x0, unsigned x1,
                                           unsigned& o0, unsigned& o1) {
    const unsigned k0 = 0u, k1 = 1u;
    const unsigned k2 = 0x1BD11BDAu ^ k0 ^ k1;  // 0x1BD11BDB
    x0 += k0; x1 += k1;
#define TF_R4(a, b, c, d)                              \
    x0 += x1; x1 = rotl32(x1, a); x1 ^= x0;            \
    x0 += x1; x1 = rotl32(x1, b); x1 ^= x0;            \
    x0 += x1; x1 = rotl32(x1, c); x1 ^= x0;            \
    x0 += x1; x1 = rotl32(x1, d); x1 ^= x0;
    TF_R4(13, 15, 26, 6)   x0 += k1; x1 += k2 + 1u;
    TF_R4(17, 29, 16, 24)  x0 += k2; x1 += k0 + 2u;
    TF_R4(13, 15, 26, 6)   x0 += k0; x1 += k1 + 3u;
    TF_R4(17, 29, 16, 24)  x0 += k1; x1 += k2 + 4u;
    TF_R4(13, 15, 26, 6)   x0 += k2; x1 += k0 + 5u;
#undef TF_R4
    o0 = x0; o1 = x1;
}

// jax.random.uniform(key(1), (16384,), f32) bits for token i.
// PARTITIONABLE layout (default in modern JAX), per jax/_src/prng.py
// _threefry_random_bits_partitionable: 64-bit counter per element
// (hi=0, lo=i for i < 2^32); for bit_width==32 the result is the XOR-FOLD
// of the two threefry output words: bits = o0 ^ o1.
// Tried and rejected by bench evidence:
//   - partitionable, bits = o1 alone        -> rel_err 0.1776 (Round 1 run)
//   - original split-counter layout          -> rel_err 0.1806 (Round 2 run)
__device__ __forceinline__ float jax_uniform(int i) {
    unsigned o0, o1;
    threefry01(0u, (unsigned)i, o0, o1);
    unsigned bits = o0 ^ o1;
    return __uint_as_float((bits >> 9) | 0x3f800000u) - 1.0f;
}

// ---------------- GEMM (fp32, packed f32x2 FMA) + fused top-2/RNG ----------------
// logits[s,e] = sum_k x[s,k] * W[e,k];  block: 128 tokens x 64 experts, K-tile 32.
// smem layout (dynamic, reused):
//   phase A: xs[BK][132] (x transposed, m-contig), ws[BK][132] (W duplicated pairs)
//   phase B: ls[BM][65]  (logits, row-major padded)
__global__ __launch_bounds__(NTHREADS, 1)
void gemm_gate_kernel(const float* __restrict__ x, const float* __restrict__ wg) {
    extern __shared__ float sm[];
    float* xs = sm;                 // BK*132 floats
    float* ws = sm + BK * 132;      // BK*132 floats

    const int tid  = threadIdx.x;
    const int tn   = tid & 15;      // N-dir thread coord (16)
    const int tm   = tid >> 4;      // M-dir thread coord (16)
    const int row0 = tm * 8;        // 8 rows per thread
    const int col0 = tn * 4;        // 4 expert cols per thread
    const int m0   = blockIdx.x * BM;
    const int lr   = tid >> 3;        // 0..31 : row within 32-row load slab
    const int lq   = (tid & 7) * 4;   // 0,4,...,28 : k offset of float4

    u64 acc[4][4];
#pragma unroll
    for (int i = 0; i < 4; i++)
#pragma unroll
        for (int j = 0; j < 4; j++) acc[i][j] = 0ull;

    float4 px[4], pw[2];
    // prefetch tile 0
#pragma unroll
    for (int p = 0; p < 4; p++)
        px[p] = *(const float4*)&x[(size_t)(m0 + p * 32 + lr) * DDIM + lq];
#pragma unroll
    for (int p = 0; p < 2; p++)
        pw[p] = *(const float4*)&wg[(size_t)(p * 32 + lr) * DDIM + lq];

    const int NT = DDIM / BK;  // 128 tiles
    for (int t = 0; t < NT; t++) {
        __syncthreads();
        // stage to smem (x transposed; W duplicated for f32x2 broadcast)
#pragma unroll
        for (int p = 0; p < 4; p++) {
            int r = p * 32 + lr;
            xs[(lq + 0) * 132 + r] = px[p].x;
            xs[(lq + 1) * 132 + r] = px[p].y;
            xs[(lq + 2) * 132 + r] = px[p].z;
            xs[(lq + 3) * 132 + r] = px[p].w;
        }
#pragma unroll
        for (int p = 0; p < 2; p++) {
            int c = 2 * (p * 32 + lr);
            float2* w0 = (float2*)&ws[(lq + 0) * 132 + c];
            float2* w1 = (float2*)&ws[(lq + 1) * 132 + c];
            float2* w2 = (float2*)&ws[(lq + 2) * 132 + c];
            float2* w3 = (float2*)&ws[(lq + 3) * 132 + c];
            *w0 = make_float2(pw[p].x, pw[p].x);
            *w1 = make_float2(pw[p].y, pw[p].y);
            *w2 = make_float2(pw[p].z, pw[p].z);
            *w3 = make_float2(pw[p].w, pw[p].w);
        }
        __syncthreads();

        // prefetch next tile while computing this one
        if (t + 1 < NT) {
            int k0 = (t + 1) * BK;
#pragma unroll
            for (int p = 0; p < 4; p++)
                px[p] = *(const float4*)&x[(size_t)(m0 + p * 32 + lr) * DDIM + k0 + lq];
#pragma unroll
            for (int p = 0; p < 2; p++)
                pw[p] = *(const float4*)&wg[(size_t)(p * 32 + lr) * DDIM + k0 + lq];
        }

        // compute: two-level accumulation (inner per K-tile) for fp32 accuracy
        u64 inner[4][4];
#pragma unroll
        for (int i = 0; i < 4; i++)
#pragma unroll
            for (int j = 0; j < 4; j++) inner[i][j] = 0ull;

#pragma unroll
        for (int k = 0; k < BK; k++) {
            ulonglong2 xa = *(const ulonglong2*)&xs[k * 132 + row0];
            ulonglong2 xb = *(const ulonglong2*)&xs[k * 132 + row0 + 4];
            ulonglong2 wa = *(const ulonglong2*)&ws[k * 132 + 2 * col0];
            ulonglong2 wb = *(const ulonglong2*)&ws[k * 132 + 2 * col0 + 4];
            u64 xp[4] = {xa.x, xa.y, xb.x, xb.y};
#pragma unroll
            for (int rp = 0; rp < 4; rp++) {
                inner[rp][0] = fma2(xp[rp], wa.x, inner[rp][0]);
                inner[rp][1] = fma2(xp[rp], wa.y, inner[rp][1]);
                inner[rp][2] = fma2(xp[rp], wb.x, inner[rp][2]);
                inner[rp][3] = fma2(xp[rp], wb.y, inner[rp][3]);
            }
        }
#pragma unroll
        for (int i = 0; i < 4; i++)
#pragma unroll
            for (int j = 0; j < 4; j++) acc[i][j] = add2(acc[i][j], inner[i][j]);
    }

    // -------- epilogue: stage logits in smem (reuse), then per-token top-2 --------
    __syncthreads();
    float* ls = sm;  // BM x 65
#pragma unroll
    for (int rp = 0; rp < 4; rp++) {
#pragma unroll
        for (int j = 0; j < 4; j++) {
            unsigned lo = (unsigned)(acc[rp][j] & 0xffffffffull);
            unsigned hi = (unsigned)(acc[rp][j] >> 32);
            ls[(row0 + 2 * rp + 0) * 65 + col0 + j] = __uint_as_float(lo);
            ls[(row0 + 2 * rp + 1) * 65 + col0 + j] = __uint_as_float(hi);
        }
    }
    __syncthreads();

    if (tid < BM) {
        const float* row = &ls[tid * 65];
        float l1 = -3.0e38f, l2 = -3.0e38f;
        int i1 = 0, i2 = 0;
#pragma unroll
        for (int e = 0; e < NEXP; e++) {
            float v = row[e];
            if (v > l1)      { l2 = l1; i2 = i1; l1 = v; i1 = e; }
            else if (v > l2) { l2 = v;  i2 = e; }
        }
        float Z = 0.0f;
#pragma unroll
        for (int e = 0; e < NEXP; e++) Z += expf(row[e] - l1);
        float g1  = 1.0f / Z;             // exp(l1-l1)/Z
        float g2  = expf(l2 - l1) / Z;
        float inv = 1.0f / (g1 + g2);
        float g1n = g1 * inv;
        float g2n = g2 * inv;

        int token = m0 + tid;
        float u = jax_uniform(token);

        g_e1[token]    = i1;
        g_e2[token]    = i2;
        g_g1n[token]   = g1n;
        g_g2n[token]   = g2n;
        g_want2[token] = (u < 2.0f * g2n) ? 1 : 0;
    }
}

// ---------------- per-expert ordered capacity scan + scatter ----------------
// One block per expert. Ballot-based ordered prefix rank over token order.
__global__ __launch_bounds__(256, 8)
void scan_write_kernel(float* __restrict__ out) {
    const int e    = blockIdx.x;
    const int tid  = threadIdx.x;
    const int lane = tid & 31;
    const int wid  = tid >> 5;
    __shared__ int wsum[8];

    // pass 1: first choice
    int base = 0;
    for (int c = 0; c < S_TOK; c += 256) {
        int  t = c + tid;
        bool m = (g_e1[t] == e);
        unsigned b = __ballot_sync(0xffffffffu, m);
        if (lane == 0) wsum[wid] = __popc(b);
        __syncthreads();
        int off = 0, tot = 0;
#pragma unroll
        for (int w = 0; w < 8; w++) {
            int s = wsum[w];
            tot += s;
            if (w < wid) off += s;
        }
        if (m) {
            int rank = base + off + __popc(b & ((1u << lane) - 1u)) + 1;
            if (rank <= CAP) out[(size_t)t * NEXP + e] = g_g1n[t];
        }
        base += tot;
        __syncthreads();
    }
    int cnt1 = base < CAP ? base : CAP;
    int rem  = CAP - cnt1;

    // pass 2: second choice (gated by want2, against remaining capacity)
    base = 0;
    for (int c = 0; c < S_TOK; c += 256) {
        int  t = c + tid;
        bool m = (g_e2[t] == e) && (g_want2[t] != 0);
        unsigned b = __ballot_sync(0xffffffffu, m);
        if (lane == 0) wsum[wid] = __popc(b);
        __syncthreads();
        int off = 0, tot = 0;
#pragma unroll
        for (int w = 0; w < 8; w++) {
            int s = wsum[w];
            tot += s;
            if (w < wid) off += s;
        }
        if (m) {
            int rank = base + off + __popc(b & ((1u << lane) - 1u)) + 1;
            if (rank <= rem) out[(size_t)t * NEXP + e] = g_g2n[t];
        }
        base += tot;
        __syncthreads();
    }
}

// ---------------- launcher ----------------
extern "C" void kernel_launch(void* const* d_in, const int* in_sizes, int n_in,
                              void* d_out, int out_size) {
    const float* x  = (const float*)d_in[0];   // [16384, 4096]
    const float* wg = (const float*)d_in[1];   // [64, 4096]
    float* out = (float*)d_out;                // [16384, 64]

    cudaMemsetAsync(out, 0, (size_t)S_TOK * NEXP * sizeof(float), 0);

    const int smem_bytes = 2 * BK * 132 * sizeof(float);  // 33792 B (>= 128*65*4 reuse)
    gemm_gate_kernel<<<S_TOK / BM, NTHREADS, smem_bytes>>>(x, wg);
    scan_write_kernel<<<NEXP, 256>>>(out);
}

// round 5
// speedup vs baseline: 2.1671x; 2.1671x over previous
#include <cuda_runtime.h>
#include <cuda_bf16.h>
#include <cstdint>

#define S_TOK 16384
#define DDIM  4096
#define NEXP  64
#define CAP   320
#define BM    128
#define BK    32
#define NCH   (DDIM / BK)   // 128 k-chunks

// smem layout: A splits (3 x 128 rows x 80B), then B splits (3 x 64 rows x 80B)
#define APITCH  80
#define A_SPLIT 10240            // 128*80
#define B_BASE  30720            // 3*A_SPLIT
#define B_SPLIT 5120             // 64*80
#define SMEM_BYTES 46080         // B_BASE + 3*B_SPLIT  (< 48KB default)

// ---------------- device scratch (static; no runtime allocation) ----------
__device__ int   g_pack[S_TOK];              // e1 | e2<<8 | want2<<16
__device__ float g_g1n[S_TOK];
__device__ float g_g2n[S_TOK];
__device__ __nv_bfloat16 g_wh[NEXP * DDIM];  // W split: hi
__device__ __nv_bfloat16 g_wm[NEXP * DDIM];  //          mid
__device__ __nv_bfloat16 g_wl[NEXP * DDIM];  //          lo

__device__ __forceinline__ uint32_t smem_u32(const void* p) {
    uint32_t a;
    asm("{ .reg .u64 t; cvta.to.shared.u64 t, %1; cvt.u32.u64 %0, t; }"
        : "=r"(a) : "l"(p));
    return a;
}

// ldmatrix x4 (no trans) — base ISA, assembles on compute_103
#define LDM4(r, addr) \
    asm volatile("ldmatrix.sync.aligned.m8n8.x4.shared.b16 {%0,%1,%2,%3}, [%4];" \
        : "=r"((r)[0]), "=r"((r)[1]), "=r"((r)[2]), "=r"((r)[3]) : "r"(addr))

// HMMA m16n8k16 bf16 -> fp32 accumulate (sm_80+ base ISA)
#define MMA_BF16(d, a, b0v, b1v) \
    asm volatile("mma.sync.aligned.m16n8k16.row.col.f32.bf16.bf16.f32 " \
        "{%0,%1,%2,%3}, {%4,%5,%6,%7}, {%8,%9}, {%0,%1,%2,%3};" \
        : "+f"((d)[0]), "+f"((d)[1]), "+f"((d)[2]), "+f"((d)[3]) \
        : "r"((a)[0]), "r"((a)[1]), "r"((a)[2]), "r"((a)[3]), \
          "r"(b0v), "r"(b1v))

// ---------------- Threefry RNG (validated Round 3) -------------------------
__device__ __forceinline__ unsigned rotl32(unsigned v, int s) {
    return (v << s) | (v >> (32 - s));
}
__device__ __forceinline__ void threefry01(unsigned x0, unsigned x1,
                                           unsigned& o0, unsigned& o1) {
    const unsigned k0 = 0u, k1 = 1u;
    const unsigned k2 = 0x1BD11BDAu ^ k0 ^ k1;
    x0 += k0; x1 += k1;
#define TF_R4(a, b, c, d)                              \
    x0 += x1; x1 = rotl32(x1, a); x1 ^= x0;            \
    x0 += x1; x1 = rotl32(x1, b); x1 ^= x0;            \
    x0 += x1; x1 = rotl32(x1, c); x1 ^= x0;            \
    x0 += x1; x1 = rotl32(x1, d); x1 ^= x0;
    TF_R4(13, 15, 26, 6)   x0 += k1; x1 += k2 + 1u;
    TF_R4(17, 29, 16, 24)  x0 += k2; x1 += k0 + 2u;
    TF_R4(13, 15, 26, 6)   x0 += k0; x1 += k1 + 3u;
    TF_R4(17, 29, 16, 24)  x0 += k1; x1 += k2 + 4u;
    TF_R4(13, 15, 26, 6)   x0 += k2; x1 += k0 + 5u;
#undef TF_R4
    o0 = x0; o1 = x1;
}
__device__ __forceinline__ float jax_uniform(int i) {
    unsigned o0, o1;
    threefry01(0u, (unsigned)i, o0, o1);
    unsigned bits = o0 ^ o1;   // partitionable layout, XOR-fold (validated)
    return __uint_as_float((bits >> 9) | 0x3f800000u) - 1.0f;
}

// ---------------- bf16 3-way split ----------------------------------------
__device__ __forceinline__ void split3(float x, uint16_t& h, uint16_t& m,
                                       uint16_t& l) {
    __nv_bfloat16 bh = __float2bfloat16(x);
    float fh = __bfloat162float(bh);
    float r1 = x - fh;
    __nv_bfloat16 bm = __float2bfloat16(r1);
    float fm = __bfloat162float(bm);
    __nv_bfloat16 bl = __float2bfloat16(r1 - fm);
    h = __bfloat16_as_ushort(bh);
    m = __bfloat16_as_ushort(bm);
    l = __bfloat16_as_ushort(bl);
}
__device__ __forceinline__ uint32_t pk2(uint16_t a, uint16_t b) {
    return (uint32_t)a | ((uint32_t)b << 16);
}

// ---------------- W pre-split ----------------------------------------------
__global__ __launch_bounds__(256)
void wprep_kernel(const float* __restrict__ wg) {
    int i = blockIdx.x * 256 + threadIdx.x;
    int base = i * 8;
    float4 a = *(const float4*)(wg + base);
    float4 b = *(const float4*)(wg + base + 4);
    float f[8] = {a.x, a.y, a.z, a.w, b.x, b.y, b.z, b.w};
    uint16_t h[8], m[8], l[8];
#pragma unroll
    for (int j = 0; j < 8; ++j) split3(f[j], h[j], m[j], l[j]);
    *(uint4*)(g_wh + base) = make_uint4(pk2(h[0],h[1]), pk2(h[2],h[3]),
                                        pk2(h[4],h[5]), pk2(h[6],h[7]));
    *(uint4*)(g_wm + base) = make_uint4(pk2(m[0],m[1]), pk2(m[2],m[3]),
                                        pk2(m[4],m[5]), pk2(m[6],m[7]));
    *(uint4*)(g_wl + base) = make_uint4(pk2(l[0],l[1]), pk2(l[2],l[3]),
                                        pk2(l[4],l[5]), pk2(l[6],l[7]));
}

// ---------------- main GEMM (mma.sync bf16, split-3) + fused gate ---------
__global__ __launch_bounds__(256, 1)
void gate_gemm_kernel(const float* __restrict__ x) {
    extern __shared__ char sm[];
    const uint32_t sb = smem_u32(sm);

    const int tid  = threadIdx.x;
    const int lane = tid & 31;
    const int wid  = tid >> 5;
    const int wm   = wid & 3;            // m-block (32 tokens)
    const int wn   = wid >> 2;           // n-block (32 experts)
    const int m0   = blockIdx.x * BM;

    // staging coords
    const int srow = tid >> 1;           // token row 0..127
    const int skh  = (tid & 1) * 16;     // k half (bf16 cols 0 / 16)
    const float* xrow = x + (size_t)(m0 + srow) * DDIM + skh;
    char* adst = sm + srow * APITCH + skh * 2;

    // ldmatrix per-lane base addresses
    const uint32_t aBase = sb + (uint32_t)(wm * 32 + (lane & 15)) * APITCH
                              + (uint32_t)(lane >> 4) * 16;
    const uint32_t bBase = sb + B_BASE
                              + (uint32_t)(wn * 32 + ((lane >> 4) << 3) + (lane & 7)) * APITCH
                              + (uint32_t)((lane >> 3) & 1) * 16;

    float macc[2][4][4];
#pragma unroll
    for (int mt = 0; mt < 2; ++mt)
#pragma unroll
        for (int nt = 0; nt < 4; ++nt)
#pragma unroll
            for (int q = 0; q < 4; ++q) macc[mt][nt][q] = 0.0f;

    // prefetch chunk 0
    float4 fx[4];
    uint4  fw[3];
#pragma unroll
    for (int q = 0; q < 4; ++q) fx[q] = *(const float4*)(xrow + q * 4);
#pragma unroll
    for (int i = 0; i < 3; ++i) {
        int g = tid + 256 * i;
        int sp = g >> 8, r = (g & 255) >> 2, un = g & 3;
        const __nv_bfloat16* ws = (sp == 0 ? g_wh : sp == 1 ? g_wm : g_wl);
        fw[i] = *(const uint4*)(ws + (size_t)r * DDIM + un * 8);
    }

    for (int c = 0; c < NCH; ++c) {
        if (c > 0) __syncthreads();      // previous chunk's compute done

        // ---- store staged x (split 3-way) ----
        {
            float f[16] = {fx[0].x, fx[0].y, fx[0].z, fx[0].w,
                           fx[1].x, fx[1].y, fx[1].z, fx[1].w,
                           fx[2].x, fx[2].y, fx[2].z, fx[2].w,
                           fx[3].x, fx[3].y, fx[3].z, fx[3].w};
            uint16_t h[16], m[16], l[16];
#pragma unroll
            for (int j = 0; j < 16; ++j) split3(f[j], h[j], m[j], l[j]);
            uint32_t hp[8], mp[8], lp[8];
#pragma unroll
            for (int j = 0; j < 8; ++j) {
                hp[j] = pk2(h[2*j], h[2*j+1]);
                mp[j] = pk2(m[2*j], m[2*j+1]);
                lp[j] = pk2(l[2*j], l[2*j+1]);
            }
            *(uint4*)(adst)                    = make_uint4(hp[0], hp[1], hp[2], hp[3]);
            *(uint4*)(adst + 16)               = make_uint4(hp[4], hp[5], hp[6], hp[7]);
            *(uint4*)(adst + A_SPLIT)          = make_uint4(mp[0], mp[1], mp[2], mp[3]);
            *(uint4*)(adst + A_SPLIT + 16)     = make_uint4(mp[4], mp[5], mp[6], mp[7]);
            *(uint4*)(adst + 2 * A_SPLIT)      = make_uint4(lp[0], lp[1], lp[2], lp[3]);
            *(uint4*)(adst + 2 * A_SPLIT + 16) = make_uint4(lp[4], lp[5], lp[6], lp[7]);
        }
        // ---- store staged W ----
#pragma unroll
        for (int i = 0; i < 3; ++i) {
            int g = tid + 256 * i;
            int sp = g >> 8, r = (g & 255) >> 2, un = g & 3;
            *(uint4*)(sm + B_BASE + sp * B_SPLIT + r * APITCH + un * 16) = fw[i];
        }
        __syncthreads();

        // ---- prefetch next chunk (overlaps compute) ----
        if (c + 1 < NCH) {
            const float* src = xrow + (c + 1) * BK;
#pragma unroll
            for (int q = 0; q < 4; ++q) fx[q] = *(const float4*)(src + q * 4);
#pragma unroll
            for (int i = 0; i < 3; ++i) {
                int g = tid + 256 * i;
                int sp = g >> 8, r = (g & 255) >> 2, un = g & 3;
                const __nv_bfloat16* ws = (sp == 0 ? g_wh : sp == 1 ? g_wm : g_wl);
                fw[i] = *(const uint4*)(ws + (size_t)r * DDIM + (c + 1) * BK + un * 8);
            }
        }

        // ---- compute: inner accs, 96 HMMA per warp ----
        float inn[2][4][4];
#pragma unroll
        for (int mt = 0; mt < 2; ++mt)
#pragma unroll
            for (int nt = 0; nt < 4; ++nt)
#pragma unroll
                for (int q = 0; q < 4; ++q) inn[mt][nt][q] = 0.0f;

#pragma unroll
        for (int kk = 0; kk < 2; ++kk) {           // two k16 steps
            uint32_t A[3][2][4];
#pragma unroll
            for (int s = 0; s < 3; ++s)
#pragma unroll
                for (int mt = 0; mt < 2; ++mt)
                    LDM4(A[s][mt], aBase + s * A_SPLIT + mt * (16 * APITCH) + kk * 32);

#pragma unroll
            for (int sbi = 0; sbi < 3; ++sbi) {
                uint32_t B0[4], B1[4];
                LDM4(B0, bBase + sbi * B_SPLIT + kk * 32);
                LDM4(B1, bBase + sbi * B_SPLIT + 16 * APITCH + kk * 32);
                const int nsa = (sbi == 0) ? 3 : (sbi == 1) ? 2 : 1;
#pragma unroll
                for (int sa = 0; sa < 3; ++sa) {
                    if (sa >= nsa) break;
#pragma unroll
                    for (int mt = 0; mt < 2; ++mt) {
                        MMA_BF16(inn[mt][0], A[sa][mt], B0[0], B0[1]);
                        MMA_BF16(inn[mt][1], A[sa][mt], B0[2], B0[3]);
                        MMA_BF16(inn[mt][2], A[sa][mt], B1[0], B1[1]);
                        MMA_BF16(inn[mt][3], A[sa][mt], B1[2], B1[3]);
                    }
                }
            }
        }
        // ---- master += inner (two-level fp32 accumulation) ----
#pragma unroll
        for (int mt = 0; mt < 2; ++mt)
#pragma unroll
            for (int nt = 0; nt < 4; ++nt)
#pragma unroll
                for (int q = 0; q < 4; ++q) macc[mt][nt][q] += inn[mt][nt][q];
    }

    // ---- epilogue: dump logits to smem, fused top-2/softmax/RNG ----
    __syncthreads();
    float* ls = (float*)sm;              // [128][66]
#pragma unroll
    for (int mt = 0; mt < 2; ++mt)
#pragma unroll
        for (int nt = 0; nt < 4; ++nt) {
            int row = wm * 32 + mt * 16 + (lane >> 2);
            int col = wn * 32 + nt * 8 + (lane & 3) * 2;
            *(float2*)(ls + row * 66 + col) =
                make_float2(macc[mt][nt][0], macc[mt][nt][1]);
            *(float2*)(ls + (row + 8) * 66 + col) =
                make_float2(macc[mt][nt][2], macc[mt][nt][3]);
        }
    __syncthreads();

    if (tid < BM) {
        const float* row = ls + tid * 66;
        float l1 = -3.0e38f, l2 = -3.0e38f;
        int i1 = 0, i2 = 0;
#pragma unroll
        for (int e = 0; e < NEXP; ++e) {
            float v = row[e];
            if (v > l1)      { l2 = l1; i2 = i1; l1 = v; i1 = e; }
            else if (v > l2) { l2 = v;  i2 = e; }
        }
        float Z = 0.0f;
#pragma unroll
        for (int e = 0; e < NEXP; ++e) Z += expf(row[e] - l1);
        float g1 = 1.0f / Z;
        float g2 = expf(l2 - l1) / Z;
        float inv = 1.0f / (g1 + g2);
        float g1n = g1 * inv;
        float g2n = g2 * inv;

        int token = m0 + tid;
        float u = jax_uniform(token);
        int want2 = (u < 2.0f * g2n) ? 1 : 0;

        g_pack[token] = i1 | (i2 << 8) | (want2 << 16);
        g_g1n[token]  = g1n;
        g_g2n[token]  = g2n;
    }
}

// ---------------- per-expert capacity scan (bitmask + block scan) ----------
__global__ __launch_bounds__(256, 4)
void scan_write_kernel(float* __restrict__ out) {
    const int e = blockIdx.x;
    const int tid = threadIdx.x, lane = tid & 31, wid = tid >> 5;
    __shared__ int ws[9];

    const int t0 = tid * 64;
    unsigned long long m1 = 0ull, m2 = 0ull;
    const int4* pk = (const int4*)(g_pack + t0);
#pragma unroll
    for (int q = 0; q < 16; ++q) {
        int4 v = pk[q];
        int vv[4] = {v.x, v.y, v.z, v.w};
#pragma unroll
        for (int u = 0; u < 4; ++u) {
            int p = vv[u];
            int j = q * 4 + u;
            if ((p & 0xff) == e) m1 |= 1ull << j;
            if (((p >> 8) & 0xff) == e && (p & 0x10000)) m2 |= 1ull << j;
        }
    }
    int cc = __popcll(m1) | (__popcll(m2) << 16);

    int xs = cc;
#pragma unroll
    for (int o = 1; o < 32; o <<= 1) {
        int y = __shfl_up_sync(0xffffffffu, xs, o);
        if (lane >= o) xs += y;
    }
    if (lane == 31) ws[wid] = xs;
    __syncthreads();
    if (tid == 0) {
        int run = 0;
        for (int w = 0; w < 8; ++w) { int t = ws[w]; ws[w] = run; run += t; }
        ws[8] = run;
    }
    __syncthreads();
    int excl = xs - cc + ws[wid];
    int tot1 = ws[8] & 0xffff;
    int rem = CAP - (tot1 < CAP ? tot1 : CAP);
    int r1 = excl & 0xffff;
    int r2 = excl >> 16;

    while (m1) {
        int j = __ffsll((long long)m1) - 1;
        m1 &= m1 - 1;
        ++r1;
        if (r1 <= CAP) out[(size_t)(t0 + j) * NEXP + e] = g_g1n[t0 + j];
    }
    while (m2) {
        int j = __ffsll((long long)m2) - 1;
        m2 &= m2 - 1;
        ++r2;
        if (r2 <= rem) out[(size_t)(t0 + j) * NEXP + e] = g_g2n[t0 + j];
    }
}

// ---------------- launcher -------------------------------------------------
extern "C" void kernel_launch(void* const* d_in, const int* in_sizes, int n_in,
                              void* d_out, int out_size) {
    const float* x  = (const float*)d_in[0];   // [16384, 4096]
    const float* wg = (const float*)d_in[1];   // [64, 4096]
    float* out = (float*)d_out;                // [16384, 64]

    cudaMemsetAsync(out, 0, (size_t)S_TOK * NEXP * sizeof(float), 0);
    wprep_kernel<<<NEXP * DDIM / (256 * 8), 256>>>(wg);
    gate_gemm_kernel<<<S_TOK / BM, 256, SMEM_BYTES>>>(x);
    scan_write_kernel<<<NEXP, 256>>>(out);
}